// round 1
// baseline (speedup 1.0000x reference)
#include <cuda_runtime.h>
#include <cstdint>

#define DIM      2048
#define NE       64
#define BK       32
#define MTILE    128
#define NTHREADS 128
#define LSTRIDE  65            // padded logits row stride (conflict-free)
#define POOLSZ   (MTILE * LSTRIDE)   // 8320 floats = 33280 B (> 6208 mainloop floats)

// packed fp32x2 FMA (Blackwell, PTX ISA 8.6, sm_100+)
__device__ __forceinline__ void ffma2(unsigned long long& d,
                                      unsigned long long a,
                                      unsigned long long b) {
    asm("fma.rn.f32x2 %0, %1, %2, %0;" : "+l"(d) : "l"(a), "l"(b));
}

__device__ __forceinline__ unsigned long long pack2(float lo, float hi) {
    unsigned long long d;
    asm("mov.b64 %0, {%1, %2};" : "=l"(d) : "f"(lo), "f"(hi));
    return d;
}

__global__ void __launch_bounds__(NTHREADS)
router_kernel(const float* __restrict__ x,
              const float* __restrict__ W,
              const float* __restrict__ bias,
              float* __restrict__ out,
              int out_size)
{
    __shared__ __align__(16) float pool[POOLSZ];
    float* xs = pool;            // [BK][128] k-major, XOR-8 swizzled (4096 floats)
    float* ws = pool + 4096;     // [64][33] expert-major, padded     (2112 floats)

    const int tid = threadIdx.x;
    const int g   = tid & 7;        // expert group: experts g, g+8, ..., g+56
    const int h   = tid >> 3;       // token group:  tokens h*8 .. h*8+7
    const int kq  = tid & 7;        // fill role: which float4 along k
    const int rr  = tid >> 3;       // fill role: which row
    const int blk = blockIdx.x;
    const int t0  = h * 8;

    unsigned long long acc[4][8];   // [token-pair][expert-col], each = 2 fp32
    #pragma unroll
    for (int p = 0; p < 4; p++)
        #pragma unroll
        for (int j = 0; j < 8; j++) acc[p][j] = 0ull;

    const float* xblk = x + (size_t)blk * MTILE * DIM;

    for (int kc = 0; kc < DIM; kc += BK) {
        __syncthreads();
        // ---- fill x tile: global [tok][k] -> smem k-major with XOR swizzle ----
        // column for (k, t) is t ^ (8 * ((k>>2) & 3)); thread's 4 k's share one column.
        {
            const int scol = 8 * (kq & 3);
            #pragma unroll
            for (int i = 0; i < 8; i++) {
                const int tA = rr + 16 * i;
                const float4 v = *reinterpret_cast<const float4*>(
                    &xblk[(size_t)tA * DIM + kc + kq * 4]);
                const int col = tA ^ scol;
                xs[(4 * kq + 0) * 128 + col] = v.x;
                xs[(4 * kq + 1) * 128 + col] = v.y;
                xs[(4 * kq + 2) * 128 + col] = v.z;
                xs[(4 * kq + 3) * 128 + col] = v.w;
            }
        }
        // ---- fill W tile: [e][33] padded, contiguous k (conflict-free) ----
        #pragma unroll
        for (int i = 0; i < 4; i++) {
            const int e = rr + 16 * i;
            const float4 v = *reinterpret_cast<const float4*>(
                &W[(size_t)e * DIM + kc + kq * 4]);
            float* wrow = &ws[e * 33 + kq * 4];
            wrow[0] = v.x; wrow[1] = v.y; wrow[2] = v.z; wrow[3] = v.w;
        }
        __syncthreads();

        // ---- mainloop: 32 k-steps, 32 FFMA2 each ----
        #pragma unroll 8
        for (int kk = 0; kk < BK; kk++) {
            const int col0 = t0 ^ (8 * ((kk >> 2) & 3));
            const ulonglong2 A0 = *reinterpret_cast<const ulonglong2*>(&xs[kk * 128 + col0]);
            const ulonglong2 A1 = *reinterpret_cast<const ulonglong2*>(&xs[kk * 128 + col0 + 4]);
            unsigned long long a[4] = {A0.x, A0.y, A1.x, A1.y};

            unsigned long long wd[8];
            #pragma unroll
            for (int j = 0; j < 8; j++) {
                const float w = ws[(g + 8 * j) * 33 + kk];
                wd[j] = pack2(w, w);
            }
            #pragma unroll
            for (int p = 0; p < 4; p++)
                #pragma unroll
                for (int j = 0; j < 8; j++)
                    ffma2(acc[p][j], a[p], wd[j]);
        }
    }

    __syncthreads();
    // ---- logits (+bias) -> padded smem [token][LSTRIDE] ----
    #pragma unroll
    for (int j = 0; j < 8; j++) {
        const int e = g + 8 * j;
        const float be = __ldg(&bias[e]);
        #pragma unroll
        for (int p = 0; p < 4; p++) {
            const float lo = __uint_as_float((unsigned)(acc[p][j] & 0xffffffffull));
            const float hi = __uint_as_float((unsigned)(acc[p][j] >> 32));
            pool[(t0 + 2 * p)     * LSTRIDE + e] = lo + be;
            pool[(t0 + 2 * p + 1) * LSTRIDE + e] = hi + be;
        }
    }
    __syncthreads();

    // ---- per-token softmax + top-2 (one token per thread) ----
    {
        const float* lg = &pool[tid * LSTRIDE];
        float v1 = -3.402823466e38f, v2 = -3.402823466e38f;
        int   i1 = 0, i2 = 0;
        #pragma unroll
        for (int e = 0; e < NE; e++) {
            const float v = lg[e];
            if (v > v1)      { v2 = v1; i2 = i1; v1 = v; i1 = e; }
            else if (v > v2) { v2 = v;  i2 = e; }
        }
        float sum = 0.0f;
        #pragma unroll
        for (int e = 0; e < NE; e++) sum += __expf(lg[e] - v1);
        const float inv = 1.0f / sum;

        const int T    = blk * MTILE + tid;
        const int half = out_size >> 1;
        // output 1: indices [16384, 2] (as float), output 2: values [16384, 2]
        out[2 * T]            = (float)i1;
        out[2 * T + 1]        = (float)i2;
        out[half + 2 * T]     = inv;                    // exp(v1 - v1) / sum
        out[half + 2 * T + 1] = __expf(v2 - v1) * inv;
    }
}

extern "C" void kernel_launch(void* const* d_in, const int* in_sizes, int n_in,
                              void* d_out, int out_size) {
    const float* x = (const float*)d_in[0];
    const float* W = (const float*)d_in[1];
    const float* b = (const float*)d_in[2];
    router_kernel<<<128, NTHREADS>>>(x, W, b, (float*)d_out, out_size);
}

// round 2
// speedup vs baseline: 1.8526x; 1.8526x over previous
#include <cuda_runtime.h>
#include <cstdint>

#define DIM      2048
#define NE       64
#define BK       32
#define MTILE    128
#define NTHREADS 256
#define LSTRIDE  65
#define POOLSZ   (MTILE * LSTRIDE)   // 8320 floats >= 6208 mainloop floats

// packed fp32x2 FMA (Blackwell, PTX ISA 8.6, sm_100+)
__device__ __forceinline__ void ffma2(unsigned long long& d,
                                      unsigned long long a,
                                      unsigned long long b) {
    asm("fma.rn.f32x2 %0, %1, %2, %0;" : "+l"(d) : "l"(a), "l"(b));
}

__device__ __forceinline__ unsigned long long pack2(float lo, float hi) {
    unsigned long long d;
    asm("mov.b64 %0, {%1, %2};" : "=l"(d) : "f"(lo), "f"(hi));
    return d;
}

__global__ void __launch_bounds__(NTHREADS)
router_kernel(const float* __restrict__ x,
              const float* __restrict__ W,
              const float* __restrict__ bias,
              float* __restrict__ out,
              int out_size)
{
    __shared__ __align__(16) float pool[POOLSZ];
    float* xs = pool;            // [BK][128] k-major, XOR-8 swizzled (4096 floats)
    float* ws = pool + 4096;     // [64][33] expert-major, padded     (2112 floats)

    const int tid = threadIdx.x;
    const int g   = tid & 7;        // expert lane: experts g, g+8, ..., g+56
    const int h   = tid >> 3;       // token group (0..31): tokens 4h .. 4h+3
    const int kq  = tid & 7;        // fill role: which float4 along k
    const int rr  = tid >> 3;       // fill role: base row (0..31)
    const int blk = blockIdx.x;
    const int t0  = h * 4;

    unsigned long long acc[2][8];   // [token-pair][expert-col]
    #pragma unroll
    for (int p = 0; p < 2; p++)
        #pragma unroll
        for (int j = 0; j < 8; j++) acc[p][j] = 0ull;

    const float* xblk = x + (size_t)blk * MTILE * DIM;

    // ---- register prefetch buffers ----
    float4 px[4];   // x: rows rr+32i, 4 k's at kc + 4*kq
    float4 pw[2];   // W: rows rr+32i

    // prefetch chunk 0
    #pragma unroll
    for (int i = 0; i < 4; i++)
        px[i] = *reinterpret_cast<const float4*>(&xblk[(size_t)(rr + 32 * i) * DIM + kq * 4]);
    #pragma unroll
    for (int i = 0; i < 2; i++)
        pw[i] = *reinterpret_cast<const float4*>(&W[(size_t)(rr + 32 * i) * DIM + kq * 4]);

    const int scol = 8 * (kq & 3);

    for (int kc = 0; kc < DIM; kc += BK) {
        // ---- store prefetched chunk to smem ----
        #pragma unroll
        for (int i = 0; i < 4; i++) {
            const int tA  = rr + 32 * i;
            const int col = tA ^ scol;
            xs[(4 * kq + 0) * 128 + col] = px[i].x;
            xs[(4 * kq + 1) * 128 + col] = px[i].y;
            xs[(4 * kq + 2) * 128 + col] = px[i].z;
            xs[(4 * kq + 3) * 128 + col] = px[i].w;
        }
        #pragma unroll
        for (int i = 0; i < 2; i++) {
            float* wrow = &ws[(rr + 32 * i) * 33 + kq * 4];
            wrow[0] = pw[i].x; wrow[1] = pw[i].y; wrow[2] = pw[i].z; wrow[3] = pw[i].w;
        }
        __syncthreads();

        // ---- issue prefetch for next chunk (overlaps compute below) ----
        const int kn = kc + BK;
        if (kn < DIM) {
            #pragma unroll
            for (int i = 0; i < 4; i++)
                px[i] = *reinterpret_cast<const float4*>(
                    &xblk[(size_t)(rr + 32 * i) * DIM + kn + kq * 4]);
            #pragma unroll
            for (int i = 0; i < 2; i++)
                pw[i] = *reinterpret_cast<const float4*>(
                    &W[(size_t)(rr + 32 * i) * DIM + kn + kq * 4]);
        }

        // ---- mainloop: 32 k-steps, 16 FFMA2 each ----
        #pragma unroll 8
        for (int kk = 0; kk < BK; kk++) {
            const int col0 = t0 ^ (8 * ((kk >> 2) & 3));
            const ulonglong2 A = *reinterpret_cast<const ulonglong2*>(&xs[kk * 128 + col0]);

            unsigned long long wd[8];
            #pragma unroll
            for (int j = 0; j < 8; j++) {
                const float w = ws[(g + 8 * j) * 33 + kk];
                wd[j] = pack2(w, w);
            }
            #pragma unroll
            for (int j = 0; j < 8; j++) ffma2(acc[0][j], A.x, wd[j]);
            #pragma unroll
            for (int j = 0; j < 8; j++) ffma2(acc[1][j], A.y, wd[j]);
        }
        __syncthreads();
    }

    // ---- logits (+bias) -> padded smem [token][LSTRIDE] ----
    #pragma unroll
    for (int j = 0; j < 8; j++) {
        const int e = g + 8 * j;
        const float be = __ldg(&bias[e]);
        #pragma unroll
        for (int p = 0; p < 2; p++) {
            const float lo = __uint_as_float((unsigned)(acc[p][j] & 0xffffffffull));
            const float hi = __uint_as_float((unsigned)(acc[p][j] >> 32));
            pool[(t0 + 2 * p)     * LSTRIDE + e] = lo + be;
            pool[(t0 + 2 * p + 1) * LSTRIDE + e] = hi + be;
        }
    }
    __syncthreads();

    // ---- per-token softmax + top-2 (threads 0..127, one token each) ----
    if (tid < MTILE) {
        const float* lg = &pool[tid * LSTRIDE];
        float v1 = -3.402823466e38f, v2 = -3.402823466e38f;
        int   i1 = 0, i2 = 0;
        #pragma unroll
        for (int e = 0; e < NE; e++) {
            const float v = lg[e];
            if (v > v1)      { v2 = v1; i2 = i1; v1 = v; i1 = e; }
            else if (v > v2) { v2 = v;  i2 = e; }
        }
        float sum = 0.0f;
        #pragma unroll
        for (int e = 0; e < NE; e++) sum += __expf(lg[e] - v1);
        const float inv = 1.0f / sum;

        const int T    = blk * MTILE + tid;
        const int half = out_size >> 1;
        out[2 * T]            = (float)i1;
        out[2 * T + 1]        = (float)i2;
        out[half + 2 * T]     = inv;
        out[half + 2 * T + 1] = __expf(v2 - v1) * inv;
    }
}

extern "C" void kernel_launch(void* const* d_in, const int* in_sizes, int n_in,
                              void* d_out, int out_size) {
    const float* x = (const float*)d_in[0];
    const float* W = (const float*)d_in[1];
    const float* b = (const float*)d_in[2];
    router_kernel<<<128, NTHREADS>>>(x, W, b, (float*)d_out, out_size);
}